// round 6
// baseline (speedup 1.0000x reference)
#include <cuda_runtime.h>

// out[n, d, t] = mean over d' of in[n, d', t]
// in: [32768, 64, 64] fp32. Compulsory: 512MB read + 512MB write, single
// mixed-stream kernel (phase-split measured slower: pure-write = 73.9% DRAM
// vs mixed = 80%). This round: 8 threads/agent, each owning TWO adjacent
// float4s -> paired back-to-back LDG.128 per d-iteration (2x bytes in flight
// per issued batch, half the issue slots per byte).

static constexpr int N_AGENTS = 32768;
static constexpr int FEAT_DIM = 64;
static constexpr int QUADS_PER_ROW = 16;   // 64 t / 4
static constexpr int F4_PER_AGENT = 1024;  // 64*64/4
static constexpr int THREADS_PER_AGENT = 8;

__global__ void __launch_bounds__(256)
mean_bcast_kernel(const float4* __restrict__ in, float4* __restrict__ out) {
    int gid = blockIdx.x * blockDim.x + threadIdx.x;   // 0 .. 32768*8-1
    int agent = gid >> 3;
    int pair = gid & 7;          // owns quads 2*pair and 2*pair+1

    const float4* __restrict__ row  = in  + (size_t)agent * F4_PER_AGENT + 2 * pair;
    float4* __restrict__       orow = out + (size_t)agent * F4_PER_AGENT + 2 * pair;

    float ax0 = 0.f, ay0 = 0.f, az0 = 0.f, aw0 = 0.f;
    float ax1 = 0.f, ay1 = 0.f, az1 = 0.f, aw1 = 0.f;
    #pragma unroll 8
    for (int d = 0; d < FEAT_DIM; d++) {
        float4 v0 = __ldcs(&row[d * QUADS_PER_ROW]);
        float4 v1 = __ldcs(&row[d * QUADS_PER_ROW + 1]);
        ax0 += v0.x; ay0 += v0.y; az0 += v0.z; aw0 += v0.w;
        ax1 += v1.x; ay1 += v1.y; az1 += v1.z; aw1 += v1.w;
    }
    const float inv = 1.0f / (float)FEAT_DIM;
    float4 m0, m1;
    m0.x = ax0 * inv; m0.y = ay0 * inv; m0.z = az0 * inv; m0.w = aw0 * inv;
    m1.x = ax1 * inv; m1.y = ay1 * inv; m1.z = az1 * inv; m1.w = aw1 * inv;

    #pragma unroll 8
    for (int d = 0; d < FEAT_DIM; d++) {
        __stcs(&orow[d * QUADS_PER_ROW],     m0);
        __stcs(&orow[d * QUADS_PER_ROW + 1], m1);
    }
}

extern "C" void kernel_launch(void* const* d_in, const int* in_sizes, int n_in,
                              void* d_out, int out_size) {
    const float4* in = (const float4*)d_in[0];
    float4* out = (float4*)d_out;
    // seq_start_end (d_in[1]) is a no-op: contiguous partition, mean is per-agent.
    int total_threads = N_AGENTS * THREADS_PER_AGENT;   // 262144
    int block = 256;
    int grid = total_threads / block;                   // 1024 blocks... 
    // NOTE: 262144 threads is below chip thread capacity; R3 showed that hurts.
    // Keep full occupancy: process agents in halves -> 2048 blocks, each thread
    // handles one (agent, pair) with agents split across 2x grid instead.
    // Simpler: 2048 blocks x 256 = 524288 threads, 2 half-depth... 
    // We instead launch 1024 blocks only if forced; here use 2048 blocks where
    // consecutive thread pairs... -- keep it simple and correct:
    mean_bcast_kernel<<<grid, block>>>(in, out);
}

// round 7
// speedup vs baseline: 1.3055x; 1.3055x over previous
#include <cuda_runtime.h>

// out[n, d, t] = mean over d' of in[n, d', t]
// in: [32768, 64, 64] fp32. Compulsory traffic: 512MB read + 512MB write.
//
// Roofline-final: 6 configurations measured; every full-occupancy variant
// saturates at 6.32-6.34 TB/s (the B300 mixed-stream DRAM ceiling, ~80% of
// 8TB/s spec), and every occupancy-reducing variant regresses:
//   R3 persistent 1024-blk grid: 76.6% DRAM (-4%)
//   R5 phase-split (pure write): 73.9% DRAM (-6% total)
//   R6 half threads, 2x footprint: 60.1% DRAM (-34%)
// This is the best measured config: 2048 blocks x 256 threads (524288 threads
// = full latency-hiding complement), 16 threads/agent, one float4 per thread,
// fully-coalesced 256B segments per half-warp, streaming cache hints.

static constexpr int N_AGENTS = 32768;
static constexpr int FEAT_DIM = 64;
static constexpr int QUADS_PER_ROW = 16;   // 64 t / 4
static constexpr int F4_PER_AGENT = 1024;  // 64*64/4

__global__ void __launch_bounds__(256)
mean_bcast_kernel(const float4* __restrict__ in, float4* __restrict__ out) {
    int gid = blockIdx.x * blockDim.x + threadIdx.x;   // 0 .. 32768*16-1
    int agent = gid >> 4;
    int tq = gid & 15;

    const float4* __restrict__ row = in + (size_t)agent * F4_PER_AGENT + tq;
    float4* __restrict__ orow = out + (size_t)agent * F4_PER_AGENT + tq;

    float ax = 0.f, ay = 0.f, az = 0.f, aw = 0.f;
    #pragma unroll 16
    for (int d = 0; d < FEAT_DIM; d++) {
        float4 v = __ldcs(&row[d * QUADS_PER_ROW]);
        ax += v.x; ay += v.y; az += v.z; aw += v.w;
    }
    const float inv = 1.0f / (float)FEAT_DIM;
    float4 m;
    m.x = ax * inv; m.y = ay * inv; m.z = az * inv; m.w = aw * inv;

    #pragma unroll 16
    for (int d = 0; d < FEAT_DIM; d++) {
        __stcs(&orow[d * QUADS_PER_ROW], m);
    }
}

extern "C" void kernel_launch(void* const* d_in, const int* in_sizes, int n_in,
                              void* d_out, int out_size) {
    const float4* in = (const float4*)d_in[0];
    float4* out = (float4*)d_out;
    // seq_start_end (d_in[1]) is a no-op: contiguous partition, mean is per-agent.
    int total_threads = N_AGENTS * QUADS_PER_ROW;   // 524288
    int block = 256;
    int grid = total_threads / block;               // 2048
    mean_bcast_kernel<<<grid, block>>>(in, out);
}

// round 8
// speedup vs baseline: 1.3086x; 1.0024x over previous
#include <cuda_runtime.h>

// out[n, d, t] = mean over d' of in[n, d', t]
// in: [32768, 64, 64] fp32. Compulsory traffic: 512MB read + 512MB write.
//
// Roofline-final family: every full-occupancy variant saturates at
// 6.32-6.34 TB/s (B300 mixed-stream DRAM ceiling, ~80% of 8TB/s spec);
// every occupancy-reducing variant regresses (R3: -4%, R5 split: -6%,
// R6 half-threads: -34%). Final sweep point: 512-thread blocks, same
// 524288-thread complement, 16 threads/agent, one float4/thread,
// fully-coalesced 256B segments per half-warp, streaming cache hints.

static constexpr int N_AGENTS = 32768;
static constexpr int FEAT_DIM = 64;
static constexpr int QUADS_PER_ROW = 16;   // 64 t / 4
static constexpr int F4_PER_AGENT = 1024;  // 64*64/4

__global__ void __launch_bounds__(512)
mean_bcast_kernel(const float4* __restrict__ in, float4* __restrict__ out) {
    int gid = blockIdx.x * blockDim.x + threadIdx.x;   // 0 .. 32768*16-1
    int agent = gid >> 4;
    int tq = gid & 15;

    const float4* __restrict__ row = in + (size_t)agent * F4_PER_AGENT + tq;
    float4* __restrict__ orow = out + (size_t)agent * F4_PER_AGENT + tq;

    float ax = 0.f, ay = 0.f, az = 0.f, aw = 0.f;
    #pragma unroll 16
    for (int d = 0; d < FEAT_DIM; d++) {
        float4 v = __ldcs(&row[d * QUADS_PER_ROW]);
        ax += v.x; ay += v.y; az += v.z; aw += v.w;
    }
    const float inv = 1.0f / (float)FEAT_DIM;
    float4 m;
    m.x = ax * inv; m.y = ay * inv; m.z = az * inv; m.w = aw * inv;

    #pragma unroll 16
    for (int d = 0; d < FEAT_DIM; d++) {
        __stcs(&orow[d * QUADS_PER_ROW], m);
    }
}

extern "C" void kernel_launch(void* const* d_in, const int* in_sizes, int n_in,
                              void* d_out, int out_size) {
    const float4* in = (const float4*)d_in[0];
    float4* out = (float4*)d_out;
    // seq_start_end (d_in[1]) is a no-op: contiguous partition, mean is per-agent.
    int total_threads = N_AGENTS * QUADS_PER_ROW;   // 524288
    int block = 512;
    int grid = total_threads / block;               // 1024
    mean_bcast_kernel<<<grid, block>>>(in, out);
}

// round 9
// speedup vs baseline: 1.3103x; 1.0013x over previous
#include <cuda_runtime.h>

// out[n, d, t] = mean over d' of in[n, d', t]
// in: [32768, 64, 64] fp32. Compulsory traffic: 512MB read + 512MB write.
//
// FINAL — at the B300 mixed-stream memory roofline. 8 measured configs:
// all full-occupancy variants (unroll 8/16, .ca/.cs, block 128/256/512)
// plateau at 6.29-6.34 TB/s DRAM (~80% of spec; 1.0737GB in ~160us); all
// occupancy- or stream-structure deviations regress (persistent grid -4%,
// read/write phase split -6% [pure-write drains at only 73.9%], half
// threads w/ 2x footprint -34%). TMA offers nothing: the LTS throughput
// cap (~6300 B/cyc) is measured path-independent on sm_103a.
//
// Best measured point: 2048 x 256 (524288 threads = full latency-hiding
// complement), 16 threads/agent, one float4 per thread, d-loop stride 256B
// -> fully-coalesced segments, streaming (.cs) hints on both directions.

static constexpr int N_AGENTS = 32768;
static constexpr int FEAT_DIM = 64;
static constexpr int QUADS_PER_ROW = 16;   // 64 t / 4
static constexpr int F4_PER_AGENT = 1024;  // 64*64/4

__global__ void __launch_bounds__(256)
mean_bcast_kernel(const float4* __restrict__ in, float4* __restrict__ out) {
    int gid = blockIdx.x * blockDim.x + threadIdx.x;   // 0 .. 32768*16-1
    int agent = gid >> 4;
    int tq = gid & 15;

    const float4* __restrict__ row = in + (size_t)agent * F4_PER_AGENT + tq;
    float4* __restrict__ orow = out + (size_t)agent * F4_PER_AGENT + tq;

    float ax = 0.f, ay = 0.f, az = 0.f, aw = 0.f;
    #pragma unroll 16
    for (int d = 0; d < FEAT_DIM; d++) {
        float4 v = __ldcs(&row[d * QUADS_PER_ROW]);
        ax += v.x; ay += v.y; az += v.z; aw += v.w;
    }
    const float inv = 1.0f / (float)FEAT_DIM;
    float4 m;
    m.x = ax * inv; m.y = ay * inv; m.z = az * inv; m.w = aw * inv;

    #pragma unroll 16
    for (int d = 0; d < FEAT_DIM; d++) {
        __stcs(&orow[d * QUADS_PER_ROW], m);
    }
}

extern "C" void kernel_launch(void* const* d_in, const int* in_sizes, int n_in,
                              void* d_out, int out_size) {
    const float4* in = (const float4*)d_in[0];
    float4* out = (float4*)d_out;
    // seq_start_end (d_in[1]) is a no-op: contiguous partition, mean is per-agent.
    int total_threads = N_AGENTS * QUADS_PER_ROW;   // 524288
    int block = 256;
    int grid = total_threads / block;               // 2048
    mean_bcast_kernel<<<grid, block>>>(in, out);
}

// round 10
// speedup vs baseline: 1.3336x; 1.0178x over previous
#include <cuda_runtime.h>

// out[n, d, t] = mean over d' of in[n, d', t]
// in: [32768, 64, 64] fp32. Compulsory traffic: 512MB read + 512MB write.
//
// At the B300 mixed-stream memory roofline (~6.3-6.4 TB/s, 80% of spec) in
// every full-occupancy config; all structural deviations regress. Final knob:
// store policy. Prior rounds used .cs (evict-first, still write-allocates in
// L2). This uses st.global.wt (write-through, no L2 allocation): output lines
// are never re-read, so allocation is pure LTS slot overhead.

static constexpr int N_AGENTS = 32768;
static constexpr int FEAT_DIM = 64;
static constexpr int QUADS_PER_ROW = 16;   // 64 t / 4
static constexpr int F4_PER_AGENT = 1024;  // 64*64/4

__global__ void __launch_bounds__(256)
mean_bcast_kernel(const float4* __restrict__ in, float4* __restrict__ out) {
    int gid = blockIdx.x * blockDim.x + threadIdx.x;   // 0 .. 32768*16-1
    int agent = gid >> 4;
    int tq = gid & 15;

    const float4* __restrict__ row = in + (size_t)agent * F4_PER_AGENT + tq;
    float4* __restrict__ orow = out + (size_t)agent * F4_PER_AGENT + tq;

    float ax = 0.f, ay = 0.f, az = 0.f, aw = 0.f;
    #pragma unroll 16
    for (int d = 0; d < FEAT_DIM; d++) {
        float4 v = __ldcs(&row[d * QUADS_PER_ROW]);
        ax += v.x; ay += v.y; az += v.z; aw += v.w;
    }
    const float inv = 1.0f / (float)FEAT_DIM;
    float4 m;
    m.x = ax * inv; m.y = ay * inv; m.z = az * inv; m.w = aw * inv;

    #pragma unroll 16
    for (int d = 0; d < FEAT_DIM; d++) {
        __stwt(&orow[d * QUADS_PER_ROW], m);
    }
}

extern "C" void kernel_launch(void* const* d_in, const int* in_sizes, int n_in,
                              void* d_out, int out_size) {
    const float4* in = (const float4*)d_in[0];
    float4* out = (float4*)d_out;
    // seq_start_end (d_in[1]) is a no-op: contiguous partition, mean is per-agent.
    int total_threads = N_AGENTS * QUADS_PER_ROW;   // 524288
    int block = 256;
    int grid = total_threads / block;               // 2048
    mean_bcast_kernel<<<grid, block>>>(in, out);
}